// round 9
// baseline (speedup 1.0000x reference)
#include <cuda_runtime.h>

#define NN    100000
#define NE    1600000
#define INF_  128
#define F2    64          // HEADS * OUT_F
#define NEG   0.2f

// ---------------- scratch (static device globals; no allocation) ------------
__device__ __align__(16) float g_feat [NN * F2];    // 25.6 MB
__device__ __align__(16) float g_rst  [NN * F2];    // 25.6 MB
__device__ __align__(16) float g_ex   [NE * 2];     // 12.8 MB
__device__ __align__(16) float g_el   [NN * 2];
__device__ __align__(16) float g_er   [NN * 2];
__device__ __align__(16) float g_denom[NN * 2];     // later holds 1/denom
__device__ float g_p[NN];
__device__ float g_q[NN];
__device__ float g_w[F2];
__device__ float g_c;

// ---------------- K0: zero accumulators + fold MLP (W1@W2, b1@W2+b2) --------
__global__ void init_all(const float* __restrict__ W1, const float* __restrict__ b1,
                         const float* __restrict__ W2, const float* __restrict__ b2) {
    int i = blockIdx.x * blockDim.x + threadIdx.x;
    if (i < NN * F2 / 4) ((float4*)g_rst)[i]   = make_float4(0.f, 0.f, 0.f, 0.f);
    if (i < NN * 2 / 4)  ((float4*)g_denom)[i] = make_float4(0.f, 0.f, 0.f, 0.f);
    if (blockIdx.x == 0) {
        int j = threadIdx.x;
        if (j < F2) {
            float s = 0.f;
            #pragma unroll
            for (int k = 0; k < 32; k++) s += W1[j * 32 + k] * W2[k];
            g_w[j] = s;
        }
        if (j == 0) {
            float c = b2[0];
            for (int k = 0; k < 32; k++) c += b1[k] * W2[k];
            g_c = c;
        }
    }
}

// ---------------- K1: feat = x @ W  (100K x 128 @ 128 x 64) -----------------
__global__ __launch_bounds__(256) void gemm_feat(const float* __restrict__ x,
                                                 const float* __restrict__ W) {
    __shared__ float As[64][65];
    __shared__ float Bs[64][64];
    int m0  = blockIdx.x * 64;
    int tid = threadIdx.x;
    int tx  = tid & 15, ty = tid >> 4;
    float acc[4][4];
    #pragma unroll
    for (int i = 0; i < 4; i++)
        #pragma unroll
        for (int j = 0; j < 4; j++) acc[i][j] = 0.f;

    for (int kc = 0; kc < INF_; kc += 64) {
        #pragma unroll
        for (int i = 0; i < 16; i++) {
            int idx = tid + i * 256;
            int m = idx >> 6, k = idx & 63;
            int gm = m0 + m;
            As[m][k] = (gm < NN) ? x[gm * INF_ + kc + k] : 0.f;
            Bs[m][k] = W[(kc + m) * F2 + k];
        }
        __syncthreads();
        #pragma unroll
        for (int kk = 0; kk < 64; kk++) {
            float4 b = *(const float4*)&Bs[kk][tx * 4];
            float a0 = As[ty * 4 + 0][kk];
            float a1 = As[ty * 4 + 1][kk];
            float a2 = As[ty * 4 + 2][kk];
            float a3 = As[ty * 4 + 3][kk];
            acc[0][0] += a0 * b.x; acc[0][1] += a0 * b.y; acc[0][2] += a0 * b.z; acc[0][3] += a0 * b.w;
            acc[1][0] += a1 * b.x; acc[1][1] += a1 * b.y; acc[1][2] += a1 * b.z; acc[1][3] += a1 * b.w;
            acc[2][0] += a2 * b.x; acc[2][1] += a2 * b.y; acc[2][2] += a2 * b.z; acc[2][3] += a2 * b.w;
            acc[3][0] += a3 * b.x; acc[3][1] += a3 * b.y; acc[3][2] += a3 * b.z; acc[3][3] += a3 * b.w;
        }
        __syncthreads();
    }
    #pragma unroll
    for (int i = 0; i < 4; i++) {
        int gm = m0 + ty * 4 + i;
        if (gm < NN)
            *(float4*)&g_feat[gm * F2 + tx * 4] =
                make_float4(acc[i][0], acc[i][1], acc[i][2], acc[i][3]);
    }
}

// ---------------- K2: el/er per node (warp per node) ------------------------
__global__ void attn_dots(const float* __restrict__ al, const float* __restrict__ ar) {
    int warp = (blockIdx.x * blockDim.x + threadIdx.x) >> 5;
    int lane = threadIdx.x & 31;
    if (warp >= NN) return;
    float f0 = g_feat[warp * F2 + lane];
    float f1 = g_feat[warp * F2 + 32 + lane];
    float el0 = f0 * al[lane],      er0 = f0 * ar[lane];
    float el1 = f1 * al[32 + lane], er1 = f1 * ar[32 + lane];
    #pragma unroll
    for (int o = 16; o > 0; o >>= 1) {
        el0 += __shfl_xor_sync(0xffffffffu, el0, o);
        er0 += __shfl_xor_sync(0xffffffffu, er0, o);
        el1 += __shfl_xor_sync(0xffffffffu, el1, o);
        er1 += __shfl_xor_sync(0xffffffffu, er1, o);
    }
    if (lane == 0) {
        g_el[warp * 2] = el0; g_el[warp * 2 + 1] = el1;
        g_er[warp * 2] = er0; g_er[warp * 2 + 1] = er1;
    }
}

// ---------------- K3: per-edge exp(e) + denom accumulation ------------------
// Max-subtraction dropped: exp(e)/sum(exp(e)) is analytically identical and
// e is tightly bounded here (std ~0.7), so no overflow risk.
__global__ void edge_ex(const int* __restrict__ src, const int* __restrict__ dst) {
    int e = blockIdx.x * blockDim.x + threadIdx.x;
    if (e >= NE) return;
    int s = src[e], d = dst[e];
    float2 elv = *(const float2*)(g_el + 2 * s);
    float2 erv = *(const float2*)(g_er + 2 * d);
    float e0 = elv.x + erv.x, e1 = elv.y + erv.y;
    e0 = (e0 > 0.f) ? e0 : NEG * e0;
    e1 = (e1 > 0.f) ? e1 : NEG * e1;
    float x0 = __expf(e0), x1 = __expf(e1);
    *(float2*)(g_ex + 2 * e) = make_float2(x0, x1);
    atomicAdd(&g_denom[2 * d],     x0);
    atomicAdd(&g_denom[2 * d + 1], x1);
}

// ---------------- K3b: invert denom once per node (kills per-edge division) -
__global__ void recip_denom() {
    int i = blockIdx.x * blockDim.x + threadIdx.x;
    if (i >= NN * 2) return;
    float d = g_denom[i];
    g_denom[i] = (d > 0.f) ? (1.f / d) : 0.f;
}

// ---------------- K4: aggregation rst[dst] += alpha * feat[src] -------------
__device__ __forceinline__ void red_add_v4(float* p, float a, float b, float c, float d) {
    asm volatile("red.global.add.v4.f32 [%0], {%1, %2, %3, %4};"
                 :: "l"(p), "f"(a), "f"(b), "f"(c), "f"(d) : "memory");
}

__global__ __launch_bounds__(256) void aggregate(const int* __restrict__ src,
                                                 const int* __restrict__ dst) {
    long long t = (long long)blockIdx.x * blockDim.x + threadIdx.x;
    int e = (int)(t >> 3);
    if (e >= NE) return;
    int g    = (int)(t & 7);
    int lane = threadIdx.x & 31;
    int leader = lane & ~7;
    int s = 0, d = 0;
    float a0 = 0.f, a1 = 0.f;
    if (lane == leader) {
        s = src[e]; d = dst[e];
        float2 exv = *(const float2*)(g_ex + 2 * e);
        float2 rdn = *(const float2*)(g_denom + 2 * d);   // holds 1/denom
        a0 = exv.x * rdn.x;
        a1 = exv.y * rdn.y;
    }
    s  = __shfl_sync(0xffffffffu, s,  leader);
    d  = __shfl_sync(0xffffffffu, d,  leader);
    a0 = __shfl_sync(0xffffffffu, a0, leader);
    a1 = __shfl_sync(0xffffffffu, a1, leader);
    float sc = (g < 4) ? a0 : a1;                 // cols 0..31 head0, 32..63 head1
    const float4* fp = (const float4*)(g_feat + s * F2 + g * 8);
    float4 f0 = fp[0], f1 = fp[1];
    float* rp = g_rst + d * F2 + g * 8;
    red_add_v4(rp,     f0.x * sc, f0.y * sc, f0.z * sc, f0.w * sc);
    red_add_v4(rp + 4, f1.x * sc, f1.y * sc, f1.z * sc, f1.w * sc);
}

// ---------------- K5: per-node h = relu(mean) -> scalars p, q ---------------
__global__ void node_pq(const float* __restrict__ bias) {
    int warp = (blockIdx.x * blockDim.x + threadIdx.x) >> 5;
    int lane = threadIdx.x & 31;
    if (warp >= NN) return;
    float r0 = g_rst[warp * F2 + lane]      + bias[lane];
    float r1 = g_rst[warp * F2 + 32 + lane] + bias[32 + lane];
    float h  = 0.5f * (r0 + r1);
    h = fmaxf(h, 0.f);
    float pv = h * g_w[lane];
    float qv = h * g_w[32 + lane];
    #pragma unroll
    for (int o = 16; o > 0; o >>= 1) {
        pv += __shfl_xor_sync(0xffffffffu, pv, o);
        qv += __shfl_xor_sync(0xffffffffu, qv, o);
    }
    if (lane == 0) { g_p[warp] = pv; g_q[warp] = qv; }
}

// ---------------- K6: score[e] = p[src] + q[dst] + c ------------------------
__global__ void edge_score(const int* __restrict__ src, const int* __restrict__ dst,
                           float* __restrict__ out) {
    int e = blockIdx.x * blockDim.x + threadIdx.x;
    if (e >= NE) return;
    out[e] = g_p[src[e]] + g_q[dst[e]] + g_c;
}

// ---------------- launch ----------------------------------------------------
extern "C" void kernel_launch(void* const* d_in, const int* in_sizes, int n_in,
                              void* d_out, int out_size) {
    const float* x       = (const float*)d_in[0];
    const float* W       = (const float*)d_in[1];
    const float* attn_l  = (const float*)d_in[2];
    const float* attn_r  = (const float*)d_in[3];
    const float* bias    = (const float*)d_in[4];
    const float* W1      = (const float*)d_in[5];
    const float* b1      = (const float*)d_in[6];
    const float* W2      = (const float*)d_in[7];
    const float* b2      = (const float*)d_in[8];
    const int*   src     = (const int*)d_in[9];
    const int*   dst     = (const int*)d_in[10];
    float*       out     = (float*)d_out;

    init_all<<<(NN * F2 / 4 + 255) / 256, 256>>>(W1, b1, W2, b2);
    gemm_feat<<<(NN + 63) / 64, 256>>>(x, W);
    attn_dots<<<(NN * 32 + 255) / 256, 256>>>(attn_l, attn_r);
    edge_ex<<<(NE + 255) / 256, 256>>>(src, dst);
    recip_denom<<<(NN * 2 + 255) / 256, 256>>>();
    aggregate<<<(NE * 8 + 255) / 256, 256>>>(src, dst);
    node_pq<<<(NN * 32 + 255) / 256, 256>>>(bias);
    edge_score<<<(NE + 255) / 256, 256>>>(src, dst, out);
}

// round 13
// speedup vs baseline: 1.0125x; 1.0125x over previous
#include <cuda_runtime.h>

#define NN    100000
#define NE    1600000
#define INF_  128
#define F2    64          // HEADS * OUT_F
#define NEG   0.2f

// ---------------- scratch (static device globals; no allocation) ------------
__device__ __align__(16) float g_feat [NN * F2];    // 25.6 MB
__device__ __align__(16) float g_rst  [NN * F2];    // 25.6 MB
__device__ __align__(16) float g_ex   [NE * 2];     // 12.8 MB
__device__ __align__(16) float g_el   [NN * 2];
__device__ __align__(16) float g_er   [NN * 2];
__device__ __align__(16) float g_denom[NN * 2];     // later holds 1/denom
__device__ float g_p[NN];
__device__ float g_q[NN];
__device__ float g_w[F2];
__device__ float g_c;

// ---------------- K0: zero accumulators + fold MLP (W1@W2, b1@W2+b2) --------
__global__ void init_all(const float* __restrict__ W1, const float* __restrict__ b1,
                         const float* __restrict__ W2, const float* __restrict__ b2) {
    int i = blockIdx.x * blockDim.x + threadIdx.x;
    if (i < NN * F2 / 4) ((float4*)g_rst)[i]   = make_float4(0.f, 0.f, 0.f, 0.f);
    if (i < NN * 2 / 4)  ((float4*)g_denom)[i] = make_float4(0.f, 0.f, 0.f, 0.f);
    if (blockIdx.x == 0) {
        int j = threadIdx.x;
        if (j < F2) {
            float s = 0.f;
            #pragma unroll
            for (int k = 0; k < 32; k++) s += W1[j * 32 + k] * W2[k];
            g_w[j] = s;
        }
        if (j == 0) {
            float c = b2[0];
            for (int k = 0; k < 32; k++) c += b1[k] * W2[k];
            g_c = c;
        }
    }
}

// ---------------- K1: feat = x @ W  (100K x 128 @ 128 x 64) -----------------
// 128x64 block tile, BK=32, 256 threads, 8x4 micro-tile.
// A staged TRANSPOSED (Ast[k][m]) so the 8-row A fragment loads as 2x LDS.128.
__global__ __launch_bounds__(256) void gemm_feat(const float* __restrict__ x,
                                                 const float* __restrict__ W) {
    __shared__ float Ast[32][132];   // [k][m], stride 132 keeps 16B alignment
    __shared__ float Bs [32][68];    // [k][n]
    int m0  = blockIdx.x * 128;
    int tid = threadIdx.x;
    int tx  = tid & 15;              // col group: cols tx*4 .. tx*4+3
    int ty  = tid >> 4;              // row group: rows ty*8 .. ty*8+7
    float acc[8][4];
    #pragma unroll
    for (int i = 0; i < 8; i++)
        #pragma unroll
        for (int j = 0; j < 4; j++) acc[i][j] = 0.f;

    for (int kc = 0; kc < INF_; kc += 32) {
        // stage A: 128 rows x 32 k (1024 float4), transposed into Ast[k][m]
        #pragma unroll
        for (int i = 0; i < 4; i++) {
            int idx = tid + i * 256;          // 0..1023
            int row = idx >> 3;               // 8 float4 per row (32 k)
            int f4  = idx & 7;
            int gm  = m0 + row;
            float4 v = (gm < NN) ? *(const float4*)&x[gm * INF_ + kc + f4 * 4]
                                 : make_float4(0.f, 0.f, 0.f, 0.f);
            Ast[f4 * 4 + 0][row] = v.x;
            Ast[f4 * 4 + 1][row] = v.y;
            Ast[f4 * 4 + 2][row] = v.z;
            Ast[f4 * 4 + 3][row] = v.w;
        }
        // stage B: 32 k x 64 n (512 float4)
        #pragma unroll
        for (int i = 0; i < 2; i++) {
            int idx = tid + i * 256;          // 0..511
            int kr  = idx >> 4;               // 16 float4 per row (64 n)
            int f4  = idx & 15;
            *(float4*)&Bs[kr][f4 * 4] =
                *(const float4*)&W[(kc + kr) * F2 + f4 * 4];
        }
        __syncthreads();
        #pragma unroll
        for (int kk = 0; kk < 32; kk++) {
            float4 b  = *(const float4*)&Bs[kk][tx * 4];
            float4 a0 = *(const float4*)&Ast[kk][ty * 8];
            float4 a1 = *(const float4*)&Ast[kk][ty * 8 + 4];
            acc[0][0] += a0.x * b.x; acc[0][1] += a0.x * b.y; acc[0][2] += a0.x * b.z; acc[0][3] += a0.x * b.w;
            acc[1][0] += a0.y * b.x; acc[1][1] += a0.y * b.y; acc[1][2] += a0.y * b.z; acc[1][3] += a0.y * b.w;
            acc[2][0] += a0.z * b.x; acc[2][1] += a0.z * b.y; acc[2][2] += a0.z * b.z; acc[2][3] += a0.z * b.w;
            acc[3][0] += a0.w * b.x; acc[3][1] += a0.w * b.y; acc[3][2] += a0.w * b.z; acc[3][3] += a0.w * b.w;
            acc[4][0] += a1.x * b.x; acc[4][1] += a1.x * b.y; acc[4][2] += a1.x * b.z; acc[4][3] += a1.x * b.w;
            acc[5][0] += a1.y * b.x; acc[5][1] += a1.y * b.y; acc[5][2] += a1.y * b.z; acc[5][3] += a1.y * b.w;
            acc[6][0] += a1.z * b.x; acc[6][1] += a1.z * b.y; acc[6][2] += a1.z * b.z; acc[6][3] += a1.z * b.w;
            acc[7][0] += a1.w * b.x; acc[7][1] += a1.w * b.y; acc[7][2] += a1.w * b.z; acc[7][3] += a1.w * b.w;
        }
        __syncthreads();
    }
    #pragma unroll
    for (int i = 0; i < 8; i++) {
        int gm = m0 + ty * 8 + i;
        if (gm < NN)
            *(float4*)&g_feat[gm * F2 + tx * 4] =
                make_float4(acc[i][0], acc[i][1], acc[i][2], acc[i][3]);
    }
}

// ---------------- K2: el/er per node (warp per node) ------------------------
__global__ void attn_dots(const float* __restrict__ al, const float* __restrict__ ar) {
    int warp = (blockIdx.x * blockDim.x + threadIdx.x) >> 5;
    int lane = threadIdx.x & 31;
    if (warp >= NN) return;
    float f0 = g_feat[warp * F2 + lane];
    float f1 = g_feat[warp * F2 + 32 + lane];
    float el0 = f0 * al[lane],      er0 = f0 * ar[lane];
    float el1 = f1 * al[32 + lane], er1 = f1 * ar[32 + lane];
    #pragma unroll
    for (int o = 16; o > 0; o >>= 1) {
        el0 += __shfl_xor_sync(0xffffffffu, el0, o);
        er0 += __shfl_xor_sync(0xffffffffu, er0, o);
        el1 += __shfl_xor_sync(0xffffffffu, el1, o);
        er1 += __shfl_xor_sync(0xffffffffu, er1, o);
    }
    if (lane == 0) {
        g_el[warp * 2] = el0; g_el[warp * 2 + 1] = el1;
        g_er[warp * 2] = er0; g_er[warp * 2 + 1] = er1;
    }
}

// ---------------- K3: per-edge exp(e) + denom accumulation ------------------
// Max-subtraction dropped: exp(e)/sum(exp(e)) is analytically identical and
// e is tightly bounded here (std ~0.7), so no overflow risk.
// denom accumulation uses a single v2 vector reduction (half the atomic ops).
__global__ void edge_ex(const int* __restrict__ src, const int* __restrict__ dst) {
    int e = blockIdx.x * blockDim.x + threadIdx.x;
    if (e >= NE) return;
    int s = src[e], d = dst[e];
    float2 elv = *(const float2*)(g_el + 2 * s);
    float2 erv = *(const float2*)(g_er + 2 * d);
    float e0 = elv.x + erv.x, e1 = elv.y + erv.y;
    e0 = (e0 > 0.f) ? e0 : NEG * e0;
    e1 = (e1 > 0.f) ? e1 : NEG * e1;
    float x0 = __expf(e0), x1 = __expf(e1);
    *(float2*)(g_ex + 2 * e) = make_float2(x0, x1);
    asm volatile("red.global.add.v2.f32 [%0], {%1, %2};"
                 :: "l"(g_denom + 2 * d), "f"(x0), "f"(x1) : "memory");
}

// ---------------- K3b: invert denom once per node (kills per-edge division) -
__global__ void recip_denom() {
    int i = blockIdx.x * blockDim.x + threadIdx.x;
    if (i >= NN * 2) return;
    float d = g_denom[i];
    g_denom[i] = (d > 0.f) ? (1.f / d) : 0.f;
}

// ---------------- K4: aggregation rst[dst] += alpha * feat[src] -------------
__device__ __forceinline__ void red_add_v4(float* p, float a, float b, float c, float d) {
    asm volatile("red.global.add.v4.f32 [%0], {%1, %2, %3, %4};"
                 :: "l"(p), "f"(a), "f"(b), "f"(c), "f"(d) : "memory");
}

__global__ __launch_bounds__(256) void aggregate(const int* __restrict__ src,
                                                 const int* __restrict__ dst) {
    long long t = (long long)blockIdx.x * blockDim.x + threadIdx.x;
    int e = (int)(t >> 3);
    if (e >= NE) return;
    int g    = (int)(t & 7);
    int lane = threadIdx.x & 31;
    int leader = lane & ~7;
    int s = 0, d = 0;
    float a0 = 0.f, a1 = 0.f;
    if (lane == leader) {
        s = src[e]; d = dst[e];
        float2 exv = *(const float2*)(g_ex + 2 * e);
        float2 rdn = *(const float2*)(g_denom + 2 * d);   // holds 1/denom
        a0 = exv.x * rdn.x;
        a1 = exv.y * rdn.y;
    }
    s  = __shfl_sync(0xffffffffu, s,  leader);
    d  = __shfl_sync(0xffffffffu, d,  leader);
    a0 = __shfl_sync(0xffffffffu, a0, leader);
    a1 = __shfl_sync(0xffffffffu, a1, leader);
    float sc = (g < 4) ? a0 : a1;                 // cols 0..31 head0, 32..63 head1
    const float4* fp = (const float4*)(g_feat + s * F2 + g * 8);
    float4 f0 = fp[0], f1 = fp[1];
    float* rp = g_rst + d * F2 + g * 8;
    red_add_v4(rp,     f0.x * sc, f0.y * sc, f0.z * sc, f0.w * sc);
    red_add_v4(rp + 4, f1.x * sc, f1.y * sc, f1.z * sc, f1.w * sc);
}

// ---------------- K5: per-node h = relu(mean) -> scalars p, q ---------------
__global__ void node_pq(const float* __restrict__ bias) {
    int warp = (blockIdx.x * blockDim.x + threadIdx.x) >> 5;
    int lane = threadIdx.x & 31;
    if (warp >= NN) return;
    float r0 = g_rst[warp * F2 + lane]      + bias[lane];
    float r1 = g_rst[warp * F2 + 32 + lane] + bias[32 + lane];
    float h  = 0.5f * (r0 + r1);
    h = fmaxf(h, 0.f);
    float pv = h * g_w[lane];
    float qv = h * g_w[32 + lane];
    #pragma unroll
    for (int o = 16; o > 0; o >>= 1) {
        pv += __shfl_xor_sync(0xffffffffu, pv, o);
        qv += __shfl_xor_sync(0xffffffffu, qv, o);
    }
    if (lane == 0) { g_p[warp] = pv; g_q[warp] = qv; }
}

// ---------------- K6: score[e] = p[src] + q[dst] + c ------------------------
__global__ void edge_score(const int* __restrict__ src, const int* __restrict__ dst,
                           float* __restrict__ out) {
    int e = blockIdx.x * blockDim.x + threadIdx.x;
    if (e >= NE) return;
    out[e] = g_p[src[e]] + g_q[dst[e]] + g_c;
}

// ---------------- launch ----------------------------------------------------
extern "C" void kernel_launch(void* const* d_in, const int* in_sizes, int n_in,
                              void* d_out, int out_size) {
    const float* x       = (const float*)d_in[0];
    const float* W       = (const float*)d_in[1];
    const float* attn_l  = (const float*)d_in[2];
    const float* attn_r  = (const float*)d_in[3];
    const float* bias    = (const float*)d_in[4];
    const float* W1      = (const float*)d_in[5];
    const float* b1      = (const float*)d_in[6];
    const float* W2      = (const float*)d_in[7];
    const float* b2      = (const float*)d_in[8];
    const int*   src     = (const int*)d_in[9];
    const int*   dst     = (const int*)d_in[10];
    float*       out     = (float*)d_out;

    init_all<<<(NN * F2 / 4 + 255) / 256, 256>>>(W1, b1, W2, b2);
    gemm_feat<<<(NN + 127) / 128, 256>>>(x, W);
    attn_dots<<<(NN * 32 + 255) / 256, 256>>>(attn_l, attn_r);
    edge_ex<<<(NE + 255) / 256, 256>>>(src, dst);
    recip_denom<<<(NN * 2 + 255) / 256, 256>>>();
    aggregate<<<(NE * 8 + 255) / 256, 256>>>(src, dst);
    node_pq<<<(NN * 32 + 255) / 256, 256>>>(bias);
    edge_score<<<(NE + 255) / 256, 256>>>(src, dst, out);
}